// round 7
// baseline (speedup 1.0000x reference)
#include <cuda_runtime.h>
#include <math.h>
#include <float.h>
#include <stdint.h>

#define C_IN   64
#define C_OUT  128
#define HH     128
#define WW     128
#define BATCH  16
#define HO     126
#define WO     126
#define LL     (HO * WO)          /* 15876 */
#define KDIM   576
#define NTOT   (BATCH * LL)       /* 254016 */
#define NCHUNK 18
#define BK     32
#define STAGE_BYTES 49152         /* A 16KB + B 32KB */

__device__ float    g_wn2[NCHUNK * C_OUT * BK];            // [chunk][co][kk] exact fp32
__device__ float    g_wA[NCHUNK * 4096];                   // tf32 bits, fragment-ordered
__device__ float    g_xt[(size_t)BATCH * HH * WW * C_IN];  // NHWC x
__device__ unsigned g_ymax[BATCH * C_OUT];                 // encoded tf32 max of y
__device__ int      g_winners[BATCH * C_OUT];

__device__ __forceinline__ uint32_t smem_u32(const void* p) {
    uint32_t a;
    asm("{ .reg .u64 t; cvta.to.shared.u64 t, %1; cvt.u32.u64 %0, t; }" : "=r"(a) : "l"(p));
    return a;
}
__device__ __forceinline__ uint32_t f2tf32(float f) {
    uint32_t r;
    asm("cvt.rna.tf32.f32 %0, %1;" : "=r"(r) : "f"(f));
    return r;
}
__device__ __forceinline__ uint32_t fenc(float f) {
    uint32_t u = __float_as_uint(f);
    return (u & 0x80000000u) ? ~u : (u | 0x80000000u);
}
__device__ __forceinline__ float fdec(uint32_t e) {
    uint32_t u = (e & 0x80000000u) ? (e ^ 0x80000000u) : ~e;
    return __uint_as_float(u);
}
#define CP_A16(dst, src)  asm volatile("cp.async.ca.shared.global [%0], [%1], 16;"    :: "r"(dst), "l"(src) : "memory")
#define CP_A16Z(dst, src) asm volatile("cp.async.ca.shared.global [%0], [%1], 16, 0;" :: "r"(dst), "l"(src) : "memory")
#define CP_COMMIT()       asm volatile("cp.async.commit_group;" ::: "memory")

__device__ __forceinline__ void mma8(float* c, uint32_t a0, uint32_t a1, uint32_t a2, uint32_t a3,
                                     uint32_t b0, uint32_t b1) {
    asm volatile("mma.sync.aligned.m16n8k8.row.col.f32.tf32.tf32.f32 "
        "{%0,%1,%2,%3}, {%4,%5,%6,%7}, {%8,%9}, {%0,%1,%2,%3};"
        : "+f"(c[0]), "+f"(c[1]), "+f"(c[2]), "+f"(c[3])
        : "r"(a0), "r"(a1), "r"(a2), "r"(a3), "r"(b0), "r"(b1));
}

// ---------------------------------------------------------------------------
// 1) Normalize filters -> exact g_wn2 + fragment-ordered tf32 g_wA; zero g_ymax
// ---------------------------------------------------------------------------
__global__ void norm_kernel(const float* __restrict__ w) {
    int co = blockIdx.x, tid = threadIdx.x;
    if (tid < 16) g_ymax[co * 16 + tid] = 0u;   // covers 128*16 = 2048
    __shared__ float red[256];
    float s = 0.f;
    for (int k = tid; k < KDIM; k += 256) { float v = w[co * KDIM + k]; s += v * v; }
    red[tid] = s;
    __syncthreads();
    for (int o = 128; o > 0; o >>= 1) { if (tid < o) red[tid] += red[tid + o]; __syncthreads(); }
    float nrm = sqrtf(red[0]);
    float inv = (nrm == 0.f) ? 1.f : (1.f / nrm);

    int mwarp = co >> 6, mt = (co >> 4) & 3;
    int regb0 = (co >> 3) & 1, lanehi = (co & 7) << 2;
    for (int idx = tid; idx < KDIM; idx += 256) {
        int c = idx >> 5, kk = idx & 31;
        int r = c >> 1, ci = ((c & 1) << 5) + kk;
        float val = w[co * KDIM + ci * 9 + r] * inv;
        g_wn2[(c * C_OUT + co) * BK + kk] = val;
        int ks = kk >> 3;
        int lane = lanehi | (kk & 3);
        int reg = regb0 | (((kk >> 2) & 1) << 1);
        g_wA[c * 4096 + ((((mwarp * 4 + mt) * 4 + ks) * 32) + lane) * 4 + reg] =
            __uint_as_float(f2tf32(val));
    }
}

// ---------------------------------------------------------------------------
// 2) NCHW -> NHWC transpose
// ---------------------------------------------------------------------------
__global__ __launch_bounds__(256) void transpose_kernel(const float* __restrict__ x) {
    __shared__ float s[128][65];
    int bh = blockIdx.x;
    int b = bh >> 7, h = bh & 127;
    int tid = threadIdx.x;
#pragma unroll 4
    for (int step = 0; step < 32; step++) {
        int ci = step * 2 + (tid >> 7);
        int wq = tid & 127;
        s[wq][ci] = x[(((size_t)(b * C_IN + ci) * HH) + h) * WW + wq];
    }
    __syncthreads();
#pragma unroll 4
    for (int step = 0; step < 32; step++) {
        int wq = step * 4 + (tid >> 6);
        int ci = tid & 63;
        g_xt[((size_t)((b * HH + h) * WW + wq)) * C_IN + ci] = s[wq][ci];
    }
}

// ---------------------------------------------------------------------------
// 3) Conv tf32 GEMM. BM=128, BN=256, BK=32. 8 warps (2m x 4n), warp 64x64.
//    3-stage cp.async pipeline. A fragment-ordered; B raw NHWC + quad-swizzle.
//    Epilogue fuses per-(b,co) tf32 max via atomicMax.
// ---------------------------------------------------------------------------
__global__ __launch_bounds__(256, 1)
void conv_mma_kernel(const float* __restrict__ bias, float* __restrict__ y) {
    extern __shared__ char smem[];
    uint32_t sbase = smem_u32(smem);

    int tid = threadIdx.x;
    int wid = tid >> 5, lane = tid & 31;
    int n0 = blockIdx.x * 256;

    // ---- B loader: thread t = row t ----
    int nld = n0 + tid;
    bool valid = (nld < NTOT);
    const float* xrow = g_xt;
    if (valid) {
        int b = nld / LL; int rem = nld - b * LL;
        int ho = rem / WO; int wo = rem - ho * WO;
        xrow = g_xt + ((size_t)(b * HH + ho) * WW + wo) * C_IN;
    }
    int swz = tid & 7;

    // ---- compute ids ----
    int mwarp = wid >> 2, nwarp = wid & 3;
    int g_id = lane >> 2, tig = lane & 3;

    float acc[4][8][4];
#pragma unroll
    for (int i = 0; i < 4; i++)
#pragma unroll
        for (int j = 0; j < 8; j++)
#pragma unroll
            for (int q = 0; q < 4; q++) acc[i][j][q] = 0.f;

    // stage issue
    auto issue = [&](int c, int st) {
        const char* asrc = (const char*)(g_wA + c * 4096) + tid * 16;
        uint32_t adst = sbase + st * STAGE_BYTES + tid * 16;
#pragma unroll
        for (int q = 0; q < 4; q++) CP_A16(adst + q * 4096, asrc + q * 4096);
        int r = c >> 1; int kh = r / 3, kw = r - kh * 3;
        uint32_t bdst = sbase + st * STAGE_BYTES + 16384 + tid * 128;
        const char* bsrc = (const char*)(xrow + (kh * WW + kw) * C_IN + ((c & 1) << 5));
        if (valid) {
#pragma unroll
            for (int q = 0; q < 8; q++) CP_A16(bdst + ((q ^ swz) * 16), bsrc + q * 16);
        } else {
#pragma unroll
            for (int q = 0; q < 8; q++) CP_A16Z(bdst + ((q ^ swz) * 16), bsrc);
        }
        CP_COMMIT();
    };

    issue(0, 0);
    issue(1, 1);

    for (int c = 0; c < NCHUNK; c++) {
        if (c + 2 < NCHUNK) {
            asm volatile("cp.async.wait_group 1;" ::: "memory");
        } else {
            asm volatile("cp.async.wait_group 0;" ::: "memory");
        }
        __syncthreads();
        if (c + 2 < NCHUNK) issue(c + 2, (c + 2) % 3);

        int st = c % 3;
        const char* Ast = smem + st * STAGE_BYTES;
        const char* Bst = Ast + 16384;
        const char* Arow = Ast + mwarp * 8192 + lane * 16;
        const char* Brow = Bst + (nwarp * 64 + g_id) * 128 + tig * 4;

#pragma unroll
        for (int ks = 0; ks < 4; ks++) {
            float4 a[4];
#pragma unroll
            for (int mt = 0; mt < 4; mt++)
                a[mt] = *(const float4*)(Arow + mt * 2048 + ks * 512);
            uint32_t b0[8], b1[8];
#pragma unroll
            for (int nt = 0; nt < 8; nt++) {
                b0[nt] = *(const uint32_t*)(Brow + nt * 1024 + (((2 * ks)     ^ g_id) * 16));
                b1[nt] = *(const uint32_t*)(Brow + nt * 1024 + (((2 * ks + 1) ^ g_id) * 16));
            }
#pragma unroll
            for (int mt = 0; mt < 4; mt++)
#pragma unroll
                for (int nt = 0; nt < 8; nt++)
                    mma8(acc[mt][nt],
                         __float_as_uint(a[mt].x), __float_as_uint(a[mt].y),
                         __float_as_uint(a[mt].z), __float_as_uint(a[mt].w),
                         b0[nt], b1[nt]);
        }
    }

    // ---- epilogue: store y + fused per-(b,co) max ----
    int nwbase = n0 + nwarp * 64;
    int bA = (nwbase < NTOT) ? (nwbase / LL) : (BATCH - 1);
#pragma unroll
    for (int mt = 0; mt < 4; mt++) {
        int co0 = mwarp * 64 + mt * 16 + g_id;
        int co1 = co0 + 8;
        float bc0 = bias[co0], bc1 = bias[co1];
        float mA0 = -FLT_MAX, mB0 = -FLT_MAX, mA1 = -FLT_MAX, mB1 = -FLT_MAX;
#pragma unroll
        for (int nt = 0; nt < 8; nt++) {
            int n = nwbase + nt * 8 + tig * 2;
            if (n >= NTOT) continue;
            int bb = n / LL;
            int l = n - bb * LL;
            size_t base = (size_t)bb * (C_OUT * LL) + l;
            float v00 = acc[mt][nt][0] + bc0, v01 = acc[mt][nt][1] + bc0;
            float v10 = acc[mt][nt][2] + bc1, v11 = acc[mt][nt][3] + bc1;
            *(float2*)&y[base + (size_t)co0 * LL] = make_float2(v00, v01);
            *(float2*)&y[base + (size_t)co1 * LL] = make_float2(v10, v11);
            float m0 = fmaxf(v00, v01), m1 = fmaxf(v10, v11);
            if (bb == bA) { mA0 = fmaxf(mA0, m0); mA1 = fmaxf(mA1, m1); }
            else          { mB0 = fmaxf(mB0, m0); mB1 = fmaxf(mB1, m1); }
        }
        mA0 = fmaxf(mA0, __shfl_xor_sync(0xffffffffu, mA0, 1));
        mA0 = fmaxf(mA0, __shfl_xor_sync(0xffffffffu, mA0, 2));
        mB0 = fmaxf(mB0, __shfl_xor_sync(0xffffffffu, mB0, 1));
        mB0 = fmaxf(mB0, __shfl_xor_sync(0xffffffffu, mB0, 2));
        mA1 = fmaxf(mA1, __shfl_xor_sync(0xffffffffu, mA1, 1));
        mA1 = fmaxf(mA1, __shfl_xor_sync(0xffffffffu, mA1, 2));
        mB1 = fmaxf(mB1, __shfl_xor_sync(0xffffffffu, mB1, 1));
        mB1 = fmaxf(mB1, __shfl_xor_sync(0xffffffffu, mB1, 2));
        if (tig == 0) {
            if (mA0 > -FLT_MAX) atomicMax(&g_ymax[bA * C_OUT + co0], fenc(mA0));
            if (mA1 > -FLT_MAX) atomicMax(&g_ymax[bA * C_OUT + co1], fenc(mA1));
            if (mB0 > -FLT_MAX && bA + 1 < BATCH) atomicMax(&g_ymax[(bA + 1) * C_OUT + co0], fenc(mB0));
            if (mB1 > -FLT_MAX && bA + 1 < BATCH) atomicMax(&g_ymax[(bA + 1) * C_OUT + co1], fenc(mB1));
        }
    }
}

// ---------------------------------------------------------------------------
// 4) Single-pass candidate scan + exact fp32 refinement
// ---------------------------------------------------------------------------
__global__ void argmax_refine_kernel(const float* __restrict__ y) {
    int bc = blockIdx.x, tid = threadIdx.x;
    const float* row = y + (size_t)bc * LL;
    const float4* row4 = (const float4*)row;
    int b = bc >> 7, co = bc & 127;
    __shared__ float sv[256];
    __shared__ int   si[256];

    float thresh = fdec(g_ymax[bc]) - 0.05f;

    float best = -FLT_MAX;
    int bi = 0x7fffffff;
    for (int i = tid; i < LL / 4; i += 256) {
        float4 v4 = row4[i];
        float vs[4] = { v4.x, v4.y, v4.z, v4.w };
#pragma unroll
        for (int j = 0; j < 4; j++) {
            if (vs[j] >= thresh) {
                int l = i * 4 + j;
                int ho = l / WO, wo = l - ho * WO;
                float acc = 0.f;
                for (int c = 0; c < NCHUNK; c++) {
                    int r = c >> 1, kh = r / 3, kw = r - kh * 3;
                    const float* wp = &g_wn2[(c * C_OUT + co) * BK];
                    const float* xp = &g_xt[((size_t)((b * HH + ho + kh) * WW) + (wo + kw)) * C_IN + ((c & 1) << 5)];
#pragma unroll
                    for (int kk = 0; kk < BK; kk++) acc += wp[kk] * xp[kk];
                }
                if (acc > best || (acc == best && l < bi)) { best = acc; bi = l; }
            }
        }
    }
    sv[tid] = best; si[tid] = bi;
    __syncthreads();
    for (int o = 128; o > 0; o >>= 1) {
        if (tid < o) {
            if (sv[tid + o] > sv[tid] || (sv[tid + o] == sv[tid] && si[tid + o] < si[tid])) {
                sv[tid] = sv[tid + o]; si[tid] = si[tid + o];
            }
        }
        __syncthreads();
    }
    if (tid == 0) g_winners[bc] = si[0];
}

// ---------------------------------------------------------------------------
// 5) delta_w[co][k] = mean_b winning patch
// ---------------------------------------------------------------------------
__global__ void deltaw_kernel(const float* __restrict__ x, float* __restrict__ out) {
    int t = blockIdx.x * blockDim.x + threadIdx.x;
    if (t >= C_OUT * KDIM) return;
    int co = t / KDIM;
    int k = t - co * KDIM;
    int ci = k / 9;
    int r = k - ci * 9;
    int kh = r / 3, kw = r - kh * 3;
    float s = 0.f;
#pragma unroll
    for (int b = 0; b < BATCH; b++) {
        int l = g_winners[b * C_OUT + co];
        int ho = l / WO;
        int wo = l - ho * WO;
        s += x[((size_t)(b * C_IN + ci) * HH + ho + kh) * WW + wo + kw];
    }
    out[(size_t)BATCH * C_OUT * LL + t] = s * (1.f / 16.f);
}

// ---------------------------------------------------------------------------
extern "C" void kernel_launch(void* const* d_in, const int* in_sizes, int n_in,
                              void* d_out, int out_size) {
    const float* x    = (const float*)d_in[0];
    const float* w    = (const float*)d_in[1];
    const float* bias = (const float*)d_in[2];
    float* out = (float*)d_out;

    cudaFuncSetAttribute(conv_mma_kernel,
                         cudaFuncAttributeMaxDynamicSharedMemorySize, 3 * STAGE_BYTES);

    norm_kernel<<<C_OUT, 256>>>(w);
    transpose_kernel<<<BATCH * HH, 256>>>(x);
    conv_mma_kernel<<<(NTOT + 255) / 256, 256, 3 * STAGE_BYTES>>>(bias, out);
    argmax_refine_kernel<<<BATCH * C_OUT, 256>>>(out);
    deltaw_kernel<<<(C_OUT * KDIM + 255) / 256, 256>>>(x, out);
}

// round 9
// speedup vs baseline: 1.3263x; 1.3263x over previous
#include <cuda_runtime.h>
#include <math.h>
#include <float.h>
#include <stdint.h>

#define C_IN   64
#define C_OUT  128
#define HH     128
#define WW     128
#define BATCH  16
#define HO     126
#define WO     126
#define LL     (HO * WO)          /* 15876 */
#define KDIM   576
#define NTOT   (BATCH * LL)       /* 254016 */
#define NCHUNK 18
#define BK     32
#define STAGE  32768              /* A 16KB + B 16KB */
#define CAP    128

__device__ float    g_wn2[NCHUNK * C_OUT * BK];            // [chunk][co][kk] exact fp32
__device__ float    g_wA[NCHUNK * 4096];                   // tf32 bits, fragment-ordered
__device__ float    g_xt[(size_t)BATCH * HH * WW * C_IN];  // NHWC x
__device__ unsigned g_ymax[BATCH * C_OUT];                 // encoded tf32 max of y
__device__ int      g_ccount[BATCH * C_OUT];
__device__ int      g_cand[BATCH * C_OUT * CAP];
__device__ int      g_winners[BATCH * C_OUT];

__device__ __forceinline__ uint32_t smem_u32(const void* p) {
    uint32_t a;
    asm("{ .reg .u64 t; cvta.to.shared.u64 t, %1; cvt.u32.u64 %0, t; }" : "=r"(a) : "l"(p));
    return a;
}
__device__ __forceinline__ uint32_t f2tf32(float f) {
    uint32_t r;
    asm("cvt.rna.tf32.f32 %0, %1;" : "=r"(r) : "f"(f));
    return r;
}
__device__ __forceinline__ uint32_t fenc(float f) {
    uint32_t u = __float_as_uint(f);
    return (u & 0x80000000u) ? ~u : (u | 0x80000000u);
}
__device__ __forceinline__ float fdec(uint32_t e) {
    uint32_t u = (e & 0x80000000u) ? (e ^ 0x80000000u) : ~e;
    return __uint_as_float(u);
}
#define CP_A16(dst, src)  asm volatile("cp.async.ca.shared.global [%0], [%1], 16;"    :: "r"(dst), "l"(src) : "memory")
#define CP_A16Z(dst, src) asm volatile("cp.async.ca.shared.global [%0], [%1], 16, 0;" :: "r"(dst), "l"(src) : "memory")
#define CP_COMMIT()       asm volatile("cp.async.commit_group;" ::: "memory")
#define CP_WAIT0()        asm volatile("cp.async.wait_group 0;" ::: "memory")

__device__ __forceinline__ void mma8(float* c, uint32_t a0, uint32_t a1, uint32_t a2, uint32_t a3,
                                     uint32_t b0, uint32_t b1) {
    asm volatile("mma.sync.aligned.m16n8k8.row.col.f32.tf32.tf32.f32 "
        "{%0,%1,%2,%3}, {%4,%5,%6,%7}, {%8,%9}, {%0,%1,%2,%3};"
        : "+f"(c[0]), "+f"(c[1]), "+f"(c[2]), "+f"(c[3])
        : "r"(a0), "r"(a1), "r"(a2), "r"(a3), "r"(b0), "r"(b1));
}

// ---------------------------------------------------------------------------
// 1) Normalize filters -> exact g_wn2 + fragment-ordered tf32 g_wA.
//    Also zero g_ymax / g_ccount.
// ---------------------------------------------------------------------------
__global__ void norm_kernel(const float* __restrict__ w) {
    int co = blockIdx.x, tid = threadIdx.x;
    if (tid < 16) { g_ymax[co * 16 + tid] = 0u; g_ccount[co * 16 + tid] = 0; }
    __shared__ float red[256];
    float s = 0.f;
    for (int k = tid; k < KDIM; k += 256) { float v = w[co * KDIM + k]; s += v * v; }
    red[tid] = s;
    __syncthreads();
    for (int o = 128; o > 0; o >>= 1) { if (tid < o) red[tid] += red[tid + o]; __syncthreads(); }
    float nrm = sqrtf(red[0]);
    float inv = (nrm == 0.f) ? 1.f : (1.f / nrm);

    int mwarp = co >> 6, mt = (co >> 4) & 3;
    int regb0 = (co >> 3) & 1, lanehi = (co & 7) << 2;
    for (int idx = tid; idx < KDIM; idx += 256) {
        int c = idx >> 5, kk = idx & 31;
        int r = c >> 1, ci = ((c & 1) << 5) + kk;
        float val = w[co * KDIM + ci * 9 + r] * inv;
        g_wn2[(c * C_OUT + co) * BK + kk] = val;
        int ks = kk >> 3;
        int lane = lanehi | (kk & 3);
        int reg = regb0 | (((kk >> 2) & 1) << 1);
        g_wA[c * 4096 + ((((mwarp * 4 + mt) * 4 + ks) * 32) + lane) * 4 + reg] =
            __uint_as_float(f2tf32(val));
    }
}

// ---------------------------------------------------------------------------
// 2) NCHW -> NHWC transpose
// ---------------------------------------------------------------------------
__global__ __launch_bounds__(256) void transpose_kernel(const float* __restrict__ x) {
    __shared__ float s[128][65];
    int bh = blockIdx.x;
    int b = bh >> 7, h = bh & 127;
    int tid = threadIdx.x;
#pragma unroll 4
    for (int step = 0; step < 32; step++) {
        int ci = step * 2 + (tid >> 7);
        int wq = tid & 127;
        s[wq][ci] = x[(((size_t)(b * C_IN + ci) * HH) + h) * WW + wq];
    }
    __syncthreads();
#pragma unroll 4
    for (int step = 0; step < 32; step++) {
        int wq = step * 4 + (tid >> 6);
        int ci = tid & 63;
        g_xt[((size_t)((b * HH + h) * WW + wq)) * C_IN + ci] = s[wq][ci];
    }
}

// ---------------------------------------------------------------------------
// 3) Conv tf32 GEMM. BM=128, BN=128, BK=32, 8 warps (2m x 4n), warp 64x32.
//    2-stage cp.async (A fragment-ordered, B raw NHWC + quad-swizzle), 2 CTA/SM.
//    Epilogue: y store + fused per-(b,co) encoded atomicMax.
// ---------------------------------------------------------------------------
__global__ __launch_bounds__(256, 2)
void conv_mma_kernel(const float* __restrict__ bias, float* __restrict__ y) {
    extern __shared__ char smem[];
    uint32_t sbase = smem_u32(smem);

    int tid = threadIdx.x;
    int wid = tid >> 5, lane = tid & 31;
    int n0 = blockIdx.x * 128;

    // ---- B loader: 2 threads per row (row = tid>>1), 64B half each ----
    int row = tid >> 1, half = tid & 1;
    int nld = n0 + row;
    bool valid = (nld < NTOT);
    const float* xrow = g_xt;
    if (valid) {
        int b = nld / LL; int rem = nld - b * LL;
        int ho = rem / WO; int wo = rem - ho * WO;
        xrow = g_xt + ((size_t)(b * HH + ho) * WW + wo) * C_IN;
    }
    int rsw = row & 7;

    // ---- compute ids ----
    int mwarp = wid >> 2, nwarp = wid & 3;
    int g_id = lane >> 2, tig = lane & 3;

    float acc[4][4][4];
#pragma unroll
    for (int i = 0; i < 4; i++)
#pragma unroll
        for (int j = 0; j < 4; j++)
#pragma unroll
            for (int q = 0; q < 4; q++) acc[i][j][q] = 0.f;

    auto issue = [&](int c, int st) {
        const char* asrc = (const char*)(g_wA + c * 4096) + tid * 16;
        uint32_t adst = sbase + st * STAGE + tid * 16;
#pragma unroll
        for (int q = 0; q < 4; q++) CP_A16(adst + q * 4096, asrc + q * 4096);
        int r = c >> 1; int kh = r / 3, kw = r - kh * 3;
        uint32_t bdst = sbase + st * STAGE + 16384 + row * 128;
        const char* bsrc = (const char*)(xrow + (kh * WW + kw) * C_IN + ((c & 1) << 5) + half * 16);
        if (valid) {
#pragma unroll
            for (int q = 0; q < 4; q++) CP_A16(bdst + (((half * 4 + q) ^ rsw) * 16), bsrc + q * 16);
        } else {
#pragma unroll
            for (int q = 0; q < 4; q++) CP_A16Z(bdst + (((half * 4 + q) ^ rsw) * 16), bsrc);
        }
        CP_COMMIT();
    };

    issue(0, 0);

    for (int c = 0; c < NCHUNK; c++) {
        CP_WAIT0();
        __syncthreads();
        if (c + 1 < NCHUNK) issue(c + 1, (c + 1) & 1);

        int st = c & 1;
        const char* Ast = smem + st * STAGE;
        const char* Arow = Ast + mwarp * 8192 + lane * 16;
        const char* Bbase = Ast + 16384 + (nwarp * 32 + g_id) * 128 + tig * 4;

#pragma unroll
        for (int ks = 0; ks < 4; ks++) {
            float4 a[4];
#pragma unroll
            for (int mt = 0; mt < 4; mt++)
                a[mt] = *(const float4*)(Arow + mt * 2048 + ks * 512);
            uint32_t b0[4], b1[4];
#pragma unroll
            for (int nt = 0; nt < 4; nt++) {
                b0[nt] = *(const uint32_t*)(Bbase + nt * 1024 + (((2 * ks)     ^ g_id) * 16));
                b1[nt] = *(const uint32_t*)(Bbase + nt * 1024 + (((2 * ks + 1) ^ g_id) * 16));
            }
#pragma unroll
            for (int mt = 0; mt < 4; mt++)
#pragma unroll
                for (int nt = 0; nt < 4; nt++)
                    mma8(acc[mt][nt],
                         __float_as_uint(a[mt].x), __float_as_uint(a[mt].y),
                         __float_as_uint(a[mt].z), __float_as_uint(a[mt].w),
                         b0[nt], b1[nt]);
        }
    }

    // ---- epilogue: store y + fused per-(b,co) max ----
    int nwbase = n0 + nwarp * 32;
    int bA = (nwbase < NTOT) ? (nwbase / LL) : (BATCH - 1);
#pragma unroll
    for (int mt = 0; mt < 4; mt++) {
        int co0 = mwarp * 64 + mt * 16 + g_id;
        int co1 = co0 + 8;
        float bc0 = bias[co0], bc1 = bias[co1];
        float mA0 = -FLT_MAX, mB0 = -FLT_MAX, mA1 = -FLT_MAX, mB1 = -FLT_MAX;
#pragma unroll
        for (int nt = 0; nt < 4; nt++) {
            int n = nwbase + nt * 8 + tig * 2;
            if (n >= NTOT) continue;
            int bb = n / LL;
            int l = n - bb * LL;
            size_t base = (size_t)bb * (C_OUT * LL) + l;
            float v00 = acc[mt][nt][0] + bc0, v01 = acc[mt][nt][1] + bc0;
            float v10 = acc[mt][nt][2] + bc1, v11 = acc[mt][nt][3] + bc1;
            *(float2*)&y[base + (size_t)co0 * LL] = make_float2(v00, v01);
            *(float2*)&y[base + (size_t)co1 * LL] = make_float2(v10, v11);
            float m0 = fmaxf(v00, v01), m1 = fmaxf(v10, v11);
            if (bb == bA) { mA0 = fmaxf(mA0, m0); mA1 = fmaxf(mA1, m1); }
            else          { mB0 = fmaxf(mB0, m0); mB1 = fmaxf(mB1, m1); }
        }
        mA0 = fmaxf(mA0, __shfl_xor_sync(0xffffffffu, mA0, 1));
        mA0 = fmaxf(mA0, __shfl_xor_sync(0xffffffffu, mA0, 2));
        mB0 = fmaxf(mB0, __shfl_xor_sync(0xffffffffu, mB0, 1));
        mB0 = fmaxf(mB0, __shfl_xor_sync(0xffffffffu, mB0, 2));
        mA1 = fmaxf(mA1, __shfl_xor_sync(0xffffffffu, mA1, 1));
        mA1 = fmaxf(mA1, __shfl_xor_sync(0xffffffffu, mA1, 2));
        mB1 = fmaxf(mB1, __shfl_xor_sync(0xffffffffu, mB1, 1));
        mB1 = fmaxf(mB1, __shfl_xor_sync(0xffffffffu, mB1, 2));
        if (tig == 0) {
            if (mA0 > -FLT_MAX) atomicMax(&g_ymax[bA * C_OUT + co0], fenc(mA0));
            if (mA1 > -FLT_MAX) atomicMax(&g_ymax[bA * C_OUT + co1], fenc(mA1));
            if (mB0 > -FLT_MAX && bA + 1 < BATCH) atomicMax(&g_ymax[(bA + 1) * C_OUT + co0], fenc(mB0));
            if (mB1 > -FLT_MAX && bA + 1 < BATCH) atomicMax(&g_ymax[(bA + 1) * C_OUT + co1], fenc(mB1));
        }
    }
}

// ---------------------------------------------------------------------------
// 4a) Streaming candidate scan: tight loop, no refinement inline.
// ---------------------------------------------------------------------------
__global__ __launch_bounds__(256) void scan_kernel(const float* __restrict__ y) {
    int bc = blockIdx.x, tid = threadIdx.x;
    const float4* row4 = (const float4*)(y + (size_t)bc * LL);
    float thresh = fdec(g_ymax[bc]) - 0.05f;

    for (int i = tid; i < LL / 4; i += 256) {
        float4 v = row4[i];
        float mx = fmaxf(fmaxf(v.x, v.y), fmaxf(v.z, v.w));
        if (mx >= thresh) {
            float vs[4] = { v.x, v.y, v.z, v.w };
#pragma unroll
            for (int j = 0; j < 4; j++) {
                if (vs[j] >= thresh) {
                    int pos = atomicAdd(&g_ccount[bc], 1);
                    if (pos < CAP) g_cand[bc * CAP + pos] = i * 4 + j;
                }
            }
        }
    }
}

// ---------------------------------------------------------------------------
// 4b) Exact fp32 refinement over candidates: one warp per (b,co).
// ---------------------------------------------------------------------------
__global__ void refine_kernel() {
    int bc = blockIdx.x, lane = threadIdx.x;
    int b = bc >> 7, co = bc & 127;
    int cnt = g_ccount[bc];
    if (cnt > CAP) cnt = CAP;

    float best = -FLT_MAX;
    int bi = 0x7fffffff;
    for (int idx = 0; idx < cnt; idx++) {
        int l = g_cand[bc * CAP + idx];
        int ho = l / WO, wo = l - ho * WO;
        float acc = 0.f;
#pragma unroll
        for (int c = 0; c < NCHUNK; c++) {
            int r = c >> 1, kh = r / 3, kw = r - kh * 3;
            acc += g_wn2[(c * C_OUT + co) * BK + lane] *
                   g_xt[((size_t)((b * HH + ho + kh) * WW) + (wo + kw)) * C_IN + ((c & 1) << 5) + lane];
        }
#pragma unroll
        for (int o = 16; o > 0; o >>= 1) acc += __shfl_xor_sync(0xffffffffu, acc, o);
        if (lane == 0) {
            if (acc > best || (acc == best && l < bi)) { best = acc; bi = l; }
        }
    }
    if (lane == 0) g_winners[bc] = bi;
}

// ---------------------------------------------------------------------------
// 5) delta_w[co][k] = mean_b winning patch
// ---------------------------------------------------------------------------
__global__ void deltaw_kernel(const float* __restrict__ x, float* __restrict__ out) {
    int t = blockIdx.x * blockDim.x + threadIdx.x;
    if (t >= C_OUT * KDIM) return;
    int co = t / KDIM;
    int k = t - co * KDIM;
    int ci = k / 9;
    int r = k - ci * 9;
    int kh = r / 3, kw = r - kh * 3;
    float s = 0.f;
#pragma unroll
    for (int b = 0; b < BATCH; b++) {
        int l = g_winners[b * C_OUT + co];
        int ho = l / WO;
        int wo = l - ho * WO;
        s += x[((size_t)(b * C_IN + ci) * HH + ho + kh) * WW + wo + kw];
    }
    out[(size_t)BATCH * C_OUT * LL + t] = s * (1.f / 16.f);
}

// ---------------------------------------------------------------------------
extern "C" void kernel_launch(void* const* d_in, const int* in_sizes, int n_in,
                              void* d_out, int out_size) {
    const float* x    = (const float*)d_in[0];
    const float* w    = (const float*)d_in[1];
    const float* bias = (const float*)d_in[2];
    float* out = (float*)d_out;

    cudaFuncSetAttribute(conv_mma_kernel,
                         cudaFuncAttributeMaxDynamicSharedMemorySize, 2 * STAGE);

    norm_kernel<<<C_OUT, 256>>>(w);
    transpose_kernel<<<BATCH * HH, 256>>>(x);
    conv_mma_kernel<<<(NTOT + 127) / 128, 256, 2 * STAGE>>>(bias, out);
    scan_kernel<<<BATCH * C_OUT, 256>>>(out);
    refine_kernel<<<BATCH * C_OUT, 32>>>();
    deltaw_kernel<<<(C_OUT * KDIM + 255) / 256, 256>>>(x, out);
}

// round 10
// speedup vs baseline: 1.8510x; 1.3956x over previous
#include <cuda_runtime.h>
#include <cuda_fp16.h>
#include <math.h>
#include <float.h>
#include <stdint.h>

#define C_IN   64
#define C_OUT  128
#define HH     128
#define WW     128
#define BATCH  16
#define HO     126
#define WO     126
#define LL     (HO * WO)          /* 15876 */
#define KDIM   576
#define NTOT   (BATCH * LL)       /* 254016 */
#define NCHUNK 18
#define BK     32
#define STAGE  16384              /* A 8KB + B 8KB */
#define CAP    128

__device__ float    g_wn2[NCHUNK * C_OUT * BK];            // [chunk][co][kk] exact fp32
__device__ uint32_t g_wAh[NCHUNK * 2048];                  // f16x2 words, fragment-ordered
__device__ float    g_xt[(size_t)BATCH * HH * WW * C_IN];  // NHWC x fp32 (refine)
__device__ __half   g_xh[(size_t)BATCH * HH * WW * C_IN];  // NHWC x fp16 (conv B)
__device__ unsigned g_ymax[BATCH * C_OUT];                 // encoded max of y
__device__ int      g_ccount[BATCH * C_OUT];
__device__ int      g_cand[BATCH * C_OUT * CAP];
__device__ int      g_winners[BATCH * C_OUT];

__device__ __forceinline__ uint32_t smem_u32(const void* p) {
    uint32_t a;
    asm("{ .reg .u64 t; cvta.to.shared.u64 t, %1; cvt.u32.u64 %0, t; }" : "=r"(a) : "l"(p));
    return a;
}
__device__ __forceinline__ uint32_t pack_h2(float lo, float hi) {
    uint32_t r;
    asm("cvt.rn.f16x2.f32 %0, %1, %2;" : "=r"(r) : "f"(hi), "f"(lo));  // d={hi,lo}
    return r;
}
__device__ __forceinline__ uint32_t fenc(float f) {
    uint32_t u = __float_as_uint(f);
    return (u & 0x80000000u) ? ~u : (u | 0x80000000u);
}
__device__ __forceinline__ float fdec(uint32_t e) {
    uint32_t u = (e & 0x80000000u) ? (e ^ 0x80000000u) : ~e;
    return __uint_as_float(u);
}
#define CP_A16(dst, src)  asm volatile("cp.async.ca.shared.global [%0], [%1], 16;"    :: "r"(dst), "l"(src) : "memory")
#define CP_A16Z(dst, src) asm volatile("cp.async.ca.shared.global [%0], [%1], 16, 0;" :: "r"(dst), "l"(src) : "memory")
#define CP_COMMIT()       asm volatile("cp.async.commit_group;" ::: "memory")

__device__ __forceinline__ void mma16(float* c, uint32_t a0, uint32_t a1, uint32_t a2, uint32_t a3,
                                      uint32_t b0, uint32_t b1) {
    asm volatile("mma.sync.aligned.m16n8k16.row.col.f32.f16.f16.f32 "
        "{%0,%1,%2,%3}, {%4,%5,%6,%7}, {%8,%9}, {%0,%1,%2,%3};"
        : "+f"(c[0]), "+f"(c[1]), "+f"(c[2]), "+f"(c[3])
        : "r"(a0), "r"(a1), "r"(a2), "r"(a3), "r"(b0), "r"(b1));
}

// ---------------------------------------------------------------------------
// 1) Normalize filters -> exact g_wn2 + fragment-ordered f16x2 g_wAh.
// ---------------------------------------------------------------------------
__global__ void norm_kernel(const float* __restrict__ w) {
    int co = blockIdx.x, tid = threadIdx.x;
    if (tid < 16) { g_ymax[co * 16 + tid] = 0u; g_ccount[co * 16 + tid] = 0; }
    __shared__ float red[256];
    float s = 0.f;
    for (int k = tid; k < KDIM; k += 256) { float v = w[co * KDIM + k]; s += v * v; }
    red[tid] = s;
    __syncthreads();
    for (int o = 128; o > 0; o >>= 1) { if (tid < o) red[tid] += red[tid + o]; __syncthreads(); }
    float nrm = sqrtf(red[0]);
    float inv = (nrm == 0.f) ? 1.f : (1.f / nrm);

    // exact copy for refinement
    for (int idx = tid; idx < KDIM; idx += 256) {
        int c = idx >> 5, kk = idx & 31;
        int r = c >> 1, ci = ((c & 1) << 5) + kk;
        g_wn2[(c * C_OUT + co) * BK + kk] = w[co * KDIM + ci * 9 + r] * inv;
    }

    // fragment-ordered f16x2 for m16n8k16
    int mwarp = co >> 6, mt = (co >> 4) & 3;
    int rowhalf = (co >> 3) & 1, groupID = co & 7;
    for (int widx = tid; widx < KDIM / 2; widx += 256) {   // 288 words per co
        int c  = widx >> 4;         // 16 words per 32-k chunk
        int wk = widx & 15;
        int ks = wk >> 3, rem = wk & 7;
        int khalf = rem >> 2, tig = rem & 3;
        int kk = ks * 16 + khalf * 8 + tig * 2;
        int r = c >> 1, ci0 = ((c & 1) << 5);
        float v0 = w[co * KDIM + (ci0 + kk)     * 9 + r] * inv;
        float v1 = w[co * KDIM + (ci0 + kk + 1) * 9 + r] * inv;
        int reg = khalf * 2 + rowhalf;
        g_wAh[c * 2048 + (((mwarp * 4 + mt) * 2 + ks) * 32 + groupID * 4 + tig) * 4 + reg] =
            pack_h2(v0, v1);
    }
}

// ---------------------------------------------------------------------------
// 2) NCHW -> NHWC transpose (fp32 for refine + fp16 for conv)
// ---------------------------------------------------------------------------
__global__ __launch_bounds__(256) void transpose_kernel(const float* __restrict__ x) {
    __shared__ float s[128][65];
    int bh = blockIdx.x;
    int b = bh >> 7, h = bh & 127;
    int tid = threadIdx.x;
#pragma unroll 4
    for (int step = 0; step < 32; step++) {
        int ci = step * 2 + (tid >> 7);
        int wq = tid & 127;
        s[wq][ci] = x[(((size_t)(b * C_IN + ci) * HH) + h) * WW + wq];
    }
    __syncthreads();
#pragma unroll 4
    for (int step = 0; step < 32; step++) {
        int wq = step * 4 + (tid >> 6);
        int ci = tid & 63;
        float v = s[wq][ci];
        size_t off = ((size_t)((b * HH + h) * WW + wq)) * C_IN + ci;
        g_xt[off] = v;
        g_xh[off] = __float2half_rn(v);
    }
}

// ---------------------------------------------------------------------------
// 3) Conv fp16 GEMM (m16n8k16). BM=128, BN=128, BK=32, 8 warps (2m x 4n),
//    warp 64x32. 3-stage cp.async, A fragment-ordered f16, B raw fp16 NHWC
//    with quad swizzle pq = q ^ ((n>>1)&3). Fused encoded atomicMax epilogue.
// ---------------------------------------------------------------------------
__global__ __launch_bounds__(256, 2)
void conv_mma_kernel(const float* __restrict__ bias, float* __restrict__ y) {
    extern __shared__ char smem[];
    uint32_t sbase = smem_u32(smem);

    int tid = threadIdx.x;
    int wid = tid >> 5, lane = tid & 31;
    int n0 = blockIdx.x * 128;

    // ---- B loader: 2 threads per row, 32B (2 quads) each ----
    int row = tid >> 1, half = tid & 1;
    int nld = n0 + row;
    bool valid = (nld < NTOT);
    const __half* xrow = g_xh;
    if (valid) {
        int b = nld / LL; int rem = nld - b * LL;
        int ho = rem / WO; int wo = rem - ho * WO;
        xrow = g_xh + ((size_t)(b * HH + ho) * WW + wo) * C_IN;
    }
    int rsw = (row >> 1) & 3;

    // ---- compute ids ----
    int mwarp = wid >> 2, nwarp = wid & 3;
    int g_id = lane >> 2, tig = lane & 3;

    float acc[4][4][4];
#pragma unroll
    for (int i = 0; i < 4; i++)
#pragma unroll
        for (int j = 0; j < 4; j++)
#pragma unroll
            for (int q = 0; q < 4; q++) acc[i][j][q] = 0.f;

    auto issue = [&](int c, int st) {
        // A: 8KB fragment-ordered, 256 threads x 32B
        const char* asrc = (const char*)(g_wAh + c * 2048) + tid * 32;
        uint32_t adst = sbase + st * STAGE + tid * 32;
        CP_A16(adst, asrc);
        CP_A16(adst + 16, asrc + 16);
        // B: 128 rows x 64B fp16, quad-swizzled
        int r = c >> 1; int kh = r / 3, kw = r - kh * 3;
        uint32_t bdst = sbase + st * STAGE + 8192 + row * 64;
        const __half* bs = xrow + (kh * WW + kw) * C_IN + ((c & 1) << 5);
#pragma unroll
        for (int qi = 0; qi < 2; qi++) {
            int q = half * 2 + qi;
            int pq = q ^ rsw;
            if (valid) CP_A16(bdst + pq * 16, (const char*)(bs + q * 8));
            else       CP_A16Z(bdst + pq * 16, (const char*)bs);
        }
        CP_COMMIT();
    };

    issue(0, 0);
    issue(1, 1);

    for (int c = 0; c < NCHUNK; c++) {
        if (c + 2 < NCHUNK) {
            asm volatile("cp.async.wait_group 1;" ::: "memory");
        } else {
            asm volatile("cp.async.wait_group 0;" ::: "memory");
        }
        __syncthreads();
        if (c + 2 < NCHUNK) issue(c + 2, (c + 2) % 3);

        int st = c % 3;
        const char* Ast = smem + st * STAGE;
        const char* Arow = Ast + mwarp * 4096 + lane * 16;
        const char* Bbase = Ast + 8192 + (nwarp * 32 + g_id) * 64 + tig * 4;
        int gsw = g_id >> 1;

#pragma unroll
        for (int ks = 0; ks < 2; ks++) {
            uint4 a[4];
#pragma unroll
            for (int mt = 0; mt < 4; mt++)
                a[mt] = *(const uint4*)(Arow + mt * 1024 + ks * 512);
            uint32_t b0[4], b1[4];
#pragma unroll
            for (int nt = 0; nt < 4; nt++) {
                b0[nt] = *(const uint32_t*)(Bbase + nt * 512 + (((2 * ks)     ^ gsw) * 16));
                b1[nt] = *(const uint32_t*)(Bbase + nt * 512 + (((2 * ks + 1) ^ gsw) * 16));
            }
#pragma unroll
            for (int mt = 0; mt < 4; mt++)
#pragma unroll
                for (int nt = 0; nt < 4; nt++)
                    mma16(acc[mt][nt], a[mt].x, a[mt].y, a[mt].z, a[mt].w,
                          b0[nt], b1[nt]);
        }
    }

    // ---- epilogue: store y + fused per-(b,co) max ----
    int nwbase = n0 + nwarp * 32;
    int bA = (nwbase < NTOT) ? (nwbase / LL) : (BATCH - 1);
#pragma unroll
    for (int mt = 0; mt < 4; mt++) {
        int co0 = mwarp * 64 + mt * 16 + g_id;
        int co1 = co0 + 8;
        float bc0 = bias[co0], bc1 = bias[co1];
        float mA0 = -FLT_MAX, mB0 = -FLT_MAX, mA1 = -FLT_MAX, mB1 = -FLT_MAX;
#pragma unroll
        for (int nt = 0; nt < 4; nt++) {
            int n = nwbase + nt * 8 + tig * 2;
            if (n >= NTOT) continue;
            int bb = n / LL;
            int l = n - bb * LL;
            size_t base = (size_t)bb * (C_OUT * LL) + l;
            float v00 = acc[mt][nt][0] + bc0, v01 = acc[mt][nt][1] + bc0;
            float v10 = acc[mt][nt][2] + bc1, v11 = acc[mt][nt][3] + bc1;
            *(float2*)&y[base + (size_t)co0 * LL] = make_float2(v00, v01);
            *(float2*)&y[base + (size_t)co1 * LL] = make_float2(v10, v11);
            float m0 = fmaxf(v00, v01), m1 = fmaxf(v10, v11);
            if (bb == bA) { mA0 = fmaxf(mA0, m0); mA1 = fmaxf(mA1, m1); }
            else          { mB0 = fmaxf(mB0, m0); mB1 = fmaxf(mB1, m1); }
        }
        mA0 = fmaxf(mA0, __shfl_xor_sync(0xffffffffu, mA0, 1));
        mA0 = fmaxf(mA0, __shfl_xor_sync(0xffffffffu, mA0, 2));
        mB0 = fmaxf(mB0, __shfl_xor_sync(0xffffffffu, mB0, 1));
        mB0 = fmaxf(mB0, __shfl_xor_sync(0xffffffffu, mB0, 2));
        mA1 = fmaxf(mA1, __shfl_xor_sync(0xffffffffu, mA1, 1));
        mA1 = fmaxf(mA1, __shfl_xor_sync(0xffffffffu, mA1, 2));
        mB1 = fmaxf(mB1, __shfl_xor_sync(0xffffffffu, mB1, 1));
        mB1 = fmaxf(mB1, __shfl_xor_sync(0xffffffffu, mB1, 2));
        if (tig == 0) {
            if (mA0 > -FLT_MAX) atomicMax(&g_ymax[bA * C_OUT + co0], fenc(mA0));
            if (mA1 > -FLT_MAX) atomicMax(&g_ymax[bA * C_OUT + co1], fenc(mA1));
            if (mB0 > -FLT_MAX && bA + 1 < BATCH) atomicMax(&g_ymax[(bA + 1) * C_OUT + co0], fenc(mB0));
            if (mB1 > -FLT_MAX && bA + 1 < BATCH) atomicMax(&g_ymax[(bA + 1) * C_OUT + co1], fenc(mB1));
        }
    }
}

// ---------------------------------------------------------------------------
// 4a) Streaming candidate scan
// ---------------------------------------------------------------------------
__global__ __launch_bounds__(256) void scan_kernel(const float* __restrict__ y) {
    int bc = blockIdx.x, tid = threadIdx.x;
    const float4* row4 = (const float4*)(y + (size_t)bc * LL);
    float thresh = fdec(g_ymax[bc]) - 0.05f;

    for (int i = tid; i < LL / 4; i += 256) {
        float4 v = row4[i];
        float mx = fmaxf(fmaxf(v.x, v.y), fmaxf(v.z, v.w));
        if (mx >= thresh) {
            float vs[4] = { v.x, v.y, v.z, v.w };
#pragma unroll
            for (int j = 0; j < 4; j++) {
                if (vs[j] >= thresh) {
                    int pos = atomicAdd(&g_ccount[bc], 1);
                    if (pos < CAP) g_cand[bc * CAP + pos] = i * 4 + j;
                }
            }
        }
    }
}

// ---------------------------------------------------------------------------
// 4b) Exact fp32 refinement over candidates: one warp per (b,co)
// ---------------------------------------------------------------------------
__global__ void refine_kernel() {
    int bc = blockIdx.x, lane = threadIdx.x;
    int b = bc >> 7, co = bc & 127;
    int cnt = g_ccount[bc];
    if (cnt > CAP) cnt = CAP;

    float best = -FLT_MAX;
    int bi = 0x7fffffff;
    for (int idx = 0; idx < cnt; idx++) {
        int l = g_cand[bc * CAP + idx];
        int ho = l / WO, wo = l - ho * WO;
        float acc = 0.f;
#pragma unroll
        for (int c = 0; c < NCHUNK; c++) {
            int r = c >> 1, kh = r / 3, kw = r - kh * 3;
            acc += g_wn2[(c * C_OUT + co) * BK + lane] *
                   g_xt[((size_t)((b * HH + ho + kh) * WW) + (wo + kw)) * C_IN + ((c & 1) << 5) + lane];
        }
#pragma unroll
        for (int o = 16; o > 0; o >>= 1) acc += __shfl_xor_sync(0xffffffffu, acc, o);
        if (lane == 0) {
            if (acc > best || (acc == best && l < bi)) { best = acc; bi = l; }
        }
    }
    if (lane == 0) g_winners[bc] = bi;
}

// ---------------------------------------------------------------------------
// 5) delta_w[co][k] = mean_b winning patch
// ---------------------------------------------------------------------------
__global__ void deltaw_kernel(const float* __restrict__ x, float* __restrict__ out) {
    int t = blockIdx.x * blockDim.x + threadIdx.x;
    if (t >= C_OUT * KDIM) return;
    int co = t / KDIM;
    int k = t - co * KDIM;
    int ci = k / 9;
    int r = k - ci * 9;
    int kh = r / 3, kw = r - kh * 3;
    float s = 0.f;
#pragma unroll
    for (int b = 0; b < BATCH; b++) {
        int l = g_winners[b * C_OUT + co];
        int ho = l / WO;
        int wo = l - ho * WO;
        s += x[((size_t)(b * C_IN + ci) * HH + ho + kh) * WW + wo + kw];
    }
    out[(size_t)BATCH * C_OUT * LL + t] = s * (1.f / 16.f);
}

// ---------------------------------------------------------------------------
extern "C" void kernel_launch(void* const* d_in, const int* in_sizes, int n_in,
                              void* d_out, int out_size) {
    const float* x    = (const float*)d_in[0];
    const float* w    = (const float*)d_in[1];
    const float* bias = (const float*)d_in[2];
    float* out = (float*)d_out;

    cudaFuncSetAttribute(conv_mma_kernel,
                         cudaFuncAttributeMaxDynamicSharedMemorySize, 3 * STAGE);

    norm_kernel<<<C_OUT, 256>>>(w);
    transpose_kernel<<<BATCH * HH, 256>>>(x);
    conv_mma_kernel<<<(NTOT + 127) / 128, 256, 3 * STAGE>>>(bias, out);
    scan_kernel<<<BATCH * C_OUT, 256>>>(out);
    refine_kernel<<<BATCH * C_OUT, 32>>>();
    deltaw_kernel<<<(C_OUT * KDIM + 255) / 256, 256>>>(x, out);
}

// round 11
// speedup vs baseline: 1.9377x; 1.0469x over previous
#include <cuda_runtime.h>
#include <cuda_fp16.h>
#include <math.h>
#include <float.h>
#include <stdint.h>

#define C_IN   64
#define C_OUT  128
#define HH     128
#define WW     128
#define BATCH  16
#define HO     126
#define WO     126
#define LL     (HO * WO)          /* 15876 */
#define KDIM   576
#define NTOT   (BATCH * LL)       /* 254016 */
#define NSEG   (NTOT / 32)        /* 7938 exactly */
#define NCHUNK 18
#define BK     32
#define STAGE  16384              /* A 8KB + B 8KB */
#define NSTAGE 4
#define CAP    128

__device__ float    g_wn2[NCHUNK * C_OUT * BK];            // [chunk][co][kk] exact fp32
__device__ uint32_t g_wAh[NCHUNK * 2048];                  // f16x2 words, fragment-ordered
__device__ float    g_xt[(size_t)BATCH * HH * WW * C_IN];  // NHWC x fp32 (refine)
__device__ __half   g_xh[(size_t)BATCH * HH * WW * C_IN];  // NHWC x fp16 (conv B)
__device__ unsigned g_ymax[BATCH * C_OUT];                 // encoded max of y
__device__ unsigned g_segmax[(size_t)C_OUT * NSEG];        // encoded per-32n-segment max
__device__ int      g_ccount[BATCH * C_OUT];
__device__ int      g_cand[BATCH * C_OUT * CAP];
__device__ int      g_winners[BATCH * C_OUT];

__device__ __forceinline__ uint32_t smem_u32(const void* p) {
    uint32_t a;
    asm("{ .reg .u64 t; cvta.to.shared.u64 t, %1; cvt.u32.u64 %0, t; }" : "=r"(a) : "l"(p));
    return a;
}
__device__ __forceinline__ uint32_t pack_h2(float lo, float hi) {
    uint32_t r;
    asm("cvt.rn.f16x2.f32 %0, %1, %2;" : "=r"(r) : "f"(hi), "f"(lo));  // d={hi,lo}
    return r;
}
__device__ __forceinline__ uint32_t fenc(float f) {
    uint32_t u = __float_as_uint(f);
    return (u & 0x80000000u) ? ~u : (u | 0x80000000u);
}
__device__ __forceinline__ float fdec(uint32_t e) {
    uint32_t u = (e & 0x80000000u) ? (e ^ 0x80000000u) : ~e;
    return __uint_as_float(u);
}
#define CP_A16(dst, src)  asm volatile("cp.async.ca.shared.global [%0], [%1], 16;"    :: "r"(dst), "l"(src) : "memory")
#define CP_A16Z(dst, src) asm volatile("cp.async.ca.shared.global [%0], [%1], 16, 0;" :: "r"(dst), "l"(src) : "memory")
#define CP_COMMIT()       asm volatile("cp.async.commit_group;" ::: "memory")

__device__ __forceinline__ void mma16(float* c, uint32_t a0, uint32_t a1, uint32_t a2, uint32_t a3,
                                      uint32_t b0, uint32_t b1) {
    asm volatile("mma.sync.aligned.m16n8k16.row.col.f32.f16.f16.f32 "
        "{%0,%1,%2,%3}, {%4,%5,%6,%7}, {%8,%9}, {%0,%1,%2,%3};"
        : "+f"(c[0]), "+f"(c[1]), "+f"(c[2]), "+f"(c[3])
        : "r"(a0), "r"(a1), "r"(a2), "r"(a3), "r"(b0), "r"(b1));
}

// ---------------------------------------------------------------------------
// 1) Normalize filters -> exact g_wn2 + fragment-ordered f16x2 g_wAh.
// ---------------------------------------------------------------------------
__global__ void norm_kernel(const float* __restrict__ w) {
    int co = blockIdx.x, tid = threadIdx.x;
    if (tid < 16) { g_ymax[co * 16 + tid] = 0u; g_ccount[co * 16 + tid] = 0; }
    __shared__ float red[256];
    float s = 0.f;
    for (int k = tid; k < KDIM; k += 256) { float v = w[co * KDIM + k]; s += v * v; }
    red[tid] = s;
    __syncthreads();
    for (int o = 128; o > 0; o >>= 1) { if (tid < o) red[tid] += red[tid + o]; __syncthreads(); }
    float nrm = sqrtf(red[0]);
    float inv = (nrm == 0.f) ? 1.f : (1.f / nrm);

    // exact copy for refinement
    for (int idx = tid; idx < KDIM; idx += 256) {
        int c = idx >> 5, kk = idx & 31;
        int r = c >> 1, ci = ((c & 1) << 5) + kk;
        g_wn2[(c * C_OUT + co) * BK + kk] = w[co * KDIM + ci * 9 + r] * inv;
    }

    // fragment-ordered f16x2 for m16n8k16
    int mwarp = co >> 6, mt = (co >> 4) & 3;
    int rowhalf = (co >> 3) & 1, groupID = co & 7;
    for (int widx = tid; widx < KDIM / 2; widx += 256) {   // 288 words per co
        int c  = widx >> 4;         // 16 words per 32-k chunk
        int wk = widx & 15;
        int ks = wk >> 3, rem = wk & 7;
        int khalf = rem >> 2, tig = rem & 3;
        int kk = ks * 16 + khalf * 8 + tig * 2;
        int r = c >> 1, ci0 = ((c & 1) << 5);
        float v0 = w[co * KDIM + (ci0 + kk)     * 9 + r] * inv;
        float v1 = w[co * KDIM + (ci0 + kk + 1) * 9 + r] * inv;
        int reg = khalf * 2 + rowhalf;
        g_wAh[c * 2048 + (((mwarp * 4 + mt) * 2 + ks) * 32 + groupID * 4 + tig) * 4 + reg] =
            pack_h2(v0, v1);
    }
}

// ---------------------------------------------------------------------------
// 2) NCHW -> NHWC transpose (fp32 for refine + fp16 for conv)
// ---------------------------------------------------------------------------
__global__ __launch_bounds__(256) void transpose_kernel(const float* __restrict__ x) {
    __shared__ float s[128][65];
    int bh = blockIdx.x;
    int b = bh >> 7, h = bh & 127;
    int tid = threadIdx.x;
#pragma unroll 4
    for (int step = 0; step < 32; step++) {
        int ci = step * 2 + (tid >> 7);
        int wq = tid & 127;
        s[wq][ci] = x[(((size_t)(b * C_IN + ci) * HH) + h) * WW + wq];
    }
    __syncthreads();
#pragma unroll 4
    for (int step = 0; step < 32; step++) {
        int wq = step * 4 + (tid >> 6);
        int ci = tid & 63;
        float v = s[wq][ci];
        size_t off = ((size_t)((b * HH + h) * WW + wq)) * C_IN + ci;
        g_xt[off] = v;
        g_xh[off] = __float2half_rn(v);
    }
}

// ---------------------------------------------------------------------------
// 3) Conv fp16 GEMM (m16n8k16). BM=128, BN=128, BK=32, 8 warps (2m x 4n),
//    warp 64x32. 4-stage cp.async. Epilogue: y + per-(b,co) atomicMax +
//    per-32n-segment max store (no atomic; unique writer per segment).
// ---------------------------------------------------------------------------
__global__ __launch_bounds__(256, 2)
void conv_mma_kernel(const float* __restrict__ bias, float* __restrict__ y) {
    extern __shared__ char smem[];
    uint32_t sbase = smem_u32(smem);

    int tid = threadIdx.x;
    int wid = tid >> 5, lane = tid & 31;
    int n0 = blockIdx.x * 128;

    // ---- B loader: 2 threads per row, 32B (2 quads) each ----
    int row = tid >> 1, half = tid & 1;
    int nld = n0 + row;
    bool valid = (nld < NTOT);
    const __half* xrow = g_xh;
    if (valid) {
        int b = nld / LL; int rem = nld - b * LL;
        int ho = rem / WO; int wo = rem - ho * WO;
        xrow = g_xh + ((size_t)(b * HH + ho) * WW + wo) * C_IN;
    }
    int rsw = (row >> 1) & 3;

    // ---- compute ids ----
    int mwarp = wid >> 2, nwarp = wid & 3;
    int g_id = lane >> 2, tig = lane & 3;

    float acc[4][4][4];
#pragma unroll
    for (int i = 0; i < 4; i++)
#pragma unroll
        for (int j = 0; j < 4; j++)
#pragma unroll
            for (int q = 0; q < 4; q++) acc[i][j][q] = 0.f;

    auto issue = [&](int c, int st) {
        const char* asrc = (const char*)(g_wAh + c * 2048) + tid * 32;
        uint32_t adst = sbase + st * STAGE + tid * 32;
        CP_A16(adst, asrc);
        CP_A16(adst + 16, asrc + 16);
        int r = c >> 1; int kh = r / 3, kw = r - kh * 3;
        uint32_t bdst = sbase + st * STAGE + 8192 + row * 64;
        const __half* bs = xrow + (kh * WW + kw) * C_IN + ((c & 1) << 5);
#pragma unroll
        for (int qi = 0; qi < 2; qi++) {
            int q = half * 2 + qi;
            int pq = q ^ rsw;
            if (valid) CP_A16(bdst + pq * 16, (const char*)(bs + q * 8));
            else       CP_A16Z(bdst + pq * 16, (const char*)bs);
        }
        CP_COMMIT();
    };

    issue(0, 0);
    issue(1, 1);
    issue(2, 2);

    for (int c = 0; c < NCHUNK; c++) {
        if (c + 3 < NCHUNK) {
            asm volatile("cp.async.wait_group 2;" ::: "memory");
        } else {
            asm volatile("cp.async.wait_group 0;" ::: "memory");
        }
        __syncthreads();
        if (c + 3 < NCHUNK) issue(c + 3, (c + 3) % NSTAGE);

        int st = c % NSTAGE;
        const char* Ast = smem + st * STAGE;
        const char* Arow = Ast + mwarp * 4096 + lane * 16;
        const char* Bbase = Ast + 8192 + (nwarp * 32 + g_id) * 64 + tig * 4;
        int gsw = g_id >> 1;

#pragma unroll
        for (int ks = 0; ks < 2; ks++) {
            uint4 a[4];
#pragma unroll
            for (int mt = 0; mt < 4; mt++)
                a[mt] = *(const uint4*)(Arow + mt * 1024 + ks * 512);
            uint32_t b0[4], b1[4];
#pragma unroll
            for (int nt = 0; nt < 4; nt++) {
                b0[nt] = *(const uint32_t*)(Bbase + nt * 512 + (((2 * ks)     ^ gsw) * 16));
                b1[nt] = *(const uint32_t*)(Bbase + nt * 512 + (((2 * ks + 1) ^ gsw) * 16));
            }
#pragma unroll
            for (int mt = 0; mt < 4; mt++)
#pragma unroll
                for (int nt = 0; nt < 4; nt++)
                    mma16(acc[mt][nt], a[mt].x, a[mt].y, a[mt].z, a[mt].w,
                          b0[nt], b1[nt]);
        }
    }

    // ---- epilogue: y store + per-(b,co) atomicMax + segment max ----
    int nwbase = n0 + nwarp * 32;
    bool segvalid = (nwbase < NTOT);
    int seg = nwbase >> 5;
    int bA = segvalid ? (nwbase / LL) : (BATCH - 1);
#pragma unroll
    for (int mt = 0; mt < 4; mt++) {
        int co0 = mwarp * 64 + mt * 16 + g_id;
        int co1 = co0 + 8;
        float bc0 = bias[co0], bc1 = bias[co1];
        float mA0 = -FLT_MAX, mB0 = -FLT_MAX, mA1 = -FLT_MAX, mB1 = -FLT_MAX;
#pragma unroll
        for (int nt = 0; nt < 4; nt++) {
            int n = nwbase + nt * 8 + tig * 2;
            if (n >= NTOT) continue;
            int bb = n / LL;
            int l = n - bb * LL;
            size_t base = (size_t)bb * (C_OUT * LL) + l;
            float v00 = acc[mt][nt][0] + bc0, v01 = acc[mt][nt][1] + bc0;
            float v10 = acc[mt][nt][2] + bc1, v11 = acc[mt][nt][3] + bc1;
            *(float2*)&y[base + (size_t)co0 * LL] = make_float2(v00, v01);
            *(float2*)&y[base + (size_t)co1 * LL] = make_float2(v10, v11);
            float m0 = fmaxf(v00, v01), m1 = fmaxf(v10, v11);
            if (bb == bA) { mA0 = fmaxf(mA0, m0); mA1 = fmaxf(mA1, m1); }
            else          { mB0 = fmaxf(mB0, m0); mB1 = fmaxf(mB1, m1); }
        }
        mA0 = fmaxf(mA0, __shfl_xor_sync(0xffffffffu, mA0, 1));
        mA0 = fmaxf(mA0, __shfl_xor_sync(0xffffffffu, mA0, 2));
        mB0 = fmaxf(mB0, __shfl_xor_sync(0xffffffffu, mB0, 1));
        mB0 = fmaxf(mB0, __shfl_xor_sync(0xffffffffu, mB0, 2));
        mA1 = fmaxf(mA1, __shfl_xor_sync(0xffffffffu, mA1, 1));
        mA1 = fmaxf(mA1, __shfl_xor_sync(0xffffffffu, mA1, 2));
        mB1 = fmaxf(mB1, __shfl_xor_sync(0xffffffffu, mB1, 1));
        mB1 = fmaxf(mB1, __shfl_xor_sync(0xffffffffu, mB1, 2));
        if (tig == 0 && segvalid) {
            g_segmax[(size_t)co0 * NSEG + seg] = fenc(fmaxf(mA0, mB0));
            g_segmax[(size_t)co1 * NSEG + seg] = fenc(fmaxf(mA1, mB1));
            if (mA0 > -FLT_MAX) atomicMax(&g_ymax[bA * C_OUT + co0], fenc(mA0));
            if (mA1 > -FLT_MAX) atomicMax(&g_ymax[bA * C_OUT + co1], fenc(mA1));
            if (mB0 > -FLT_MAX && bA + 1 < BATCH) atomicMax(&g_ymax[(bA + 1) * C_OUT + co0], fenc(mB0));
            if (mB1 > -FLT_MAX && bA + 1 < BATCH) atomicMax(&g_ymax[(bA + 1) * C_OUT + co1], fenc(mB1));
        }
    }
}

// ---------------------------------------------------------------------------
// 4a) Segment-max driven candidate scan: reads 4MB of segmax instead of y.
// ---------------------------------------------------------------------------
__global__ __launch_bounds__(256) void scan_kernel(const float* __restrict__ y) {
    int bc = blockIdx.x, tid = threadIdx.x;
    int b = bc >> 7, co = bc & 127;
    const float* row = y + (size_t)bc * LL;
    float thresh = fdec(g_ymax[bc]) - 0.05f;

    int n_lo = b * LL, n_hi = n_lo + LL;
    int s0 = n_lo >> 5, s1 = (n_hi - 1) >> 5;
    const unsigned* sm = &g_segmax[(size_t)co * NSEG];

    for (int s = s0 + tid; s <= s1; s += 256) {
        if (fdec(sm[s]) >= thresh) {
            int a = s * 32;     if (a < n_lo) a = n_lo;
            int e = s * 32 + 32; if (e > n_hi) e = n_hi;
            for (int n = a; n < e; n++) {
                float v = row[n - n_lo];
                if (v >= thresh) {
                    int pos = atomicAdd(&g_ccount[bc], 1);
                    if (pos < CAP) g_cand[bc * CAP + pos] = n - n_lo;
                }
            }
        }
    }
}

// ---------------------------------------------------------------------------
// 4b) Exact fp32 refinement over candidates: one warp per (b,co)
// ---------------------------------------------------------------------------
__global__ void refine_kernel() {
    int bc = blockIdx.x, lane = threadIdx.x;
    int b = bc >> 7, co = bc & 127;
    int cnt = g_ccount[bc];
    if (cnt > CAP) cnt = CAP;

    float best = -FLT_MAX;
    int bi = 0x7fffffff;
    for (int idx = 0; idx < cnt; idx++) {
        int l = g_cand[bc * CAP + idx];
        int ho = l / WO, wo = l - ho * WO;
        float acc = 0.f;
#pragma unroll
        for (int c = 0; c < NCHUNK; c++) {
            int r = c >> 1, kh = r / 3, kw = r - kh * 3;
            acc += g_wn2[(c * C_OUT + co) * BK + lane] *
                   g_xt[((size_t)((b * HH + ho + kh) * WW) + (wo + kw)) * C_IN + ((c & 1) << 5) + lane];
        }
#pragma unroll
        for (int o = 16; o > 0; o >>= 1) acc += __shfl_xor_sync(0xffffffffu, acc, o);
        if (lane == 0) {
            if (acc > best || (acc == best && l < bi)) { best = acc; bi = l; }
        }
    }
    if (lane == 0) g_winners[bc] = bi;
}

// ---------------------------------------------------------------------------
// 5) delta_w[co][k] = mean_b winning patch
// ---------------------------------------------------------------------------
__global__ void deltaw_kernel(const float* __restrict__ x, float* __restrict__ out) {
    int t = blockIdx.x * blockDim.x + threadIdx.x;
    if (t >= C_OUT * KDIM) return;
    int co = t / KDIM;
    int k = t - co * KDIM;
    int ci = k / 9;
    int r = k - ci * 9;
    int kh = r / 3, kw = r - kh * 3;
    float s = 0.f;
#pragma unroll
    for (int b = 0; b < BATCH; b++) {
        int l = g_winners[b * C_OUT + co];
        int ho = l / WO;
        int wo = l - ho * WO;
        s += x[((size_t)(b * C_IN + ci) * HH + ho + kh) * WW + wo + kw];
    }
    out[(size_t)BATCH * C_OUT * LL + t] = s * (1.f / 16.f);
}

// ---------------------------------------------------------------------------
extern "C" void kernel_launch(void* const* d_in, const int* in_sizes, int n_in,
                              void* d_out, int out_size) {
    const float* x    = (const float*)d_in[0];
    const float* w    = (const float*)d_in[1];
    const float* bias = (const float*)d_in[2];
    float* out = (float*)d_out;

    cudaFuncSetAttribute(conv_mma_kernel,
                         cudaFuncAttributeMaxDynamicSharedMemorySize, NSTAGE * STAGE);

    norm_kernel<<<C_OUT, 256>>>(w);
    transpose_kernel<<<BATCH * HH, 256>>>(x);
    conv_mma_kernel<<<(NTOT + 127) / 128, 256, NSTAGE * STAGE>>>(bias, out);
    scan_kernel<<<BATCH * C_OUT, 256>>>(out);
    refine_kernel<<<BATCH * C_OUT, 32>>>();
    deltaw_kernel<<<(C_OUT * KDIM + 255) / 256, 256>>>(x, out);
}

// round 12
// speedup vs baseline: 2.0672x; 1.0668x over previous
#include <cuda_runtime.h>
#include <cuda_fp16.h>
#include <math.h>
#include <float.h>
#include <stdint.h>

#define C_IN   64
#define C_OUT  128
#define HH     128
#define WW     128
#define BATCH  16
#define HO     126
#define WO     126
#define LL     (HO * WO)          /* 15876 */
#define KDIM   576
#define NTOT   (BATCH * LL)       /* 254016 */
#define NSEG   (NTOT / 32)        /* 7938 exactly */
#define NCHUNK 9                  /* BK=64 chunks, one per (kh,kw) */
#define STAGE  32768              /* A 16KB + B 16KB */
#define NSTAGE 3
#define CAP    128

__device__ float    g_wn2[18 * C_OUT * 32];                // [c18][co][kk] exact fp32 (refine)
__device__ uint32_t g_wAh[NCHUNK * 4096];                  // f16x2 words, fragment-ordered
__device__ __half   g_xh[(size_t)BATCH * HH * WW * C_IN];  // NHWC x fp16 (conv B)
__device__ unsigned g_ymax[BATCH * C_OUT];                 // encoded max of y
__device__ unsigned g_segmax[(size_t)C_OUT * NSEG];        // encoded per-32n-segment max
__device__ int      g_winners[BATCH * C_OUT];

__device__ __forceinline__ uint32_t smem_u32(const void* p) {
    uint32_t a;
    asm("{ .reg .u64 t; cvta.to.shared.u64 t, %1; cvt.u32.u64 %0, t; }" : "=r"(a) : "l"(p));
    return a;
}
__device__ __forceinline__ uint32_t pack_h2(float lo, float hi) {
    uint32_t r;
    asm("cvt.rn.f16x2.f32 %0, %1, %2;" : "=r"(r) : "f"(hi), "f"(lo));  // d={hi,lo}
    return r;
}
__device__ __forceinline__ uint32_t fenc(float f) {
    uint32_t u = __float_as_uint(f);
    return (u & 0x80000000u) ? ~u : (u | 0x80000000u);
}
__device__ __forceinline__ float fdec(uint32_t e) {
    uint32_t u = (e & 0x80000000u) ? (e ^ 0x80000000u) : ~e;
    return __uint_as_float(u);
}
#define CP_A16(dst, src)  asm volatile("cp.async.ca.shared.global [%0], [%1], 16;"    :: "r"(dst), "l"(src) : "memory")
#define CP_A16Z(dst, src) asm volatile("cp.async.ca.shared.global [%0], [%1], 16, 0;" :: "r"(dst), "l"(src) : "memory")
#define CP_COMMIT()       asm volatile("cp.async.commit_group;" ::: "memory")

__device__ __forceinline__ void mma16(float* c, uint32_t a0, uint32_t a1, uint32_t a2, uint32_t a3,
                                      uint32_t b0, uint32_t b1) {
    asm volatile("mma.sync.aligned.m16n8k16.row.col.f32.f16.f16.f32 "
        "{%0,%1,%2,%3}, {%4,%5,%6,%7}, {%8,%9}, {%0,%1,%2,%3};"
        : "+f"(c[0]), "+f"(c[1]), "+f"(c[2]), "+f"(c[3])
        : "r"(a0), "r"(a1), "r"(a2), "r"(a3), "r"(b0), "r"(b1));
}

// ---------------------------------------------------------------------------
// 1) Normalize filters -> exact g_wn2 (18-chunk layout for refine) +
//    fragment-ordered f16x2 g_wAh (9-chunk BK=64 layout for conv).
// ---------------------------------------------------------------------------
__global__ void norm_kernel(const float* __restrict__ w) {
    int co = blockIdx.x, tid = threadIdx.x;
    if (tid < 16) g_ymax[co * 16 + tid] = 0u;   // covers 128*16 = 2048
    __shared__ float red[256];
    float s = 0.f;
    for (int k = tid; k < KDIM; k += 256) { float v = w[co * KDIM + k]; s += v * v; }
    red[tid] = s;
    __syncthreads();
    for (int o = 128; o > 0; o >>= 1) { if (tid < o) red[tid] += red[tid + o]; __syncthreads(); }
    float nrm = sqrtf(red[0]);
    float inv = (nrm == 0.f) ? 1.f : (1.f / nrm);

    // exact copy for refinement: [c18][co][kk], ci = (c&1)*32+kk, r = c>>1
    for (int idx = tid; idx < KDIM; idx += 256) {
        int c = idx >> 5, kk = idx & 31;
        int r = c >> 1, ci = ((c & 1) << 5) + kk;
        g_wn2[(c * C_OUT + co) * 32 + kk] = w[co * KDIM + ci * 9 + r] * inv;
    }

    // fragment-ordered f16x2 for m16n8k16, BK=64: chunk c = (kh,kw), 64 ci
    int mwarp = co >> 6, mt = (co >> 4) & 3;
    int rowhalf = (co >> 3) & 1, groupID = co & 7;
    for (int widx = tid; widx < KDIM / 2; widx += 256) {   // 288 words per co
        int c  = widx >> 5;          // 32 words per 64-k chunk
        int wk = widx & 31;
        int ks = wk >> 3, khalf = (wk >> 2) & 1, tig = wk & 3;
        int kk = ks * 16 + khalf * 8 + tig * 2;            // ci pair base
        float v0 = w[co * KDIM + kk       * 9 + c] * inv;
        float v1 = w[co * KDIM + (kk + 1) * 9 + c] * inv;
        int reg = khalf * 2 + rowhalf;
        g_wAh[c * 4096 + (((mwarp * 4 + mt) * 4 + ks) * 32 + groupID * 4 + tig) * 4 + reg] =
            pack_h2(v0, v1);
    }
}

// ---------------------------------------------------------------------------
// 2) NCHW -> NHWC fp16 transpose (conv B only)
// ---------------------------------------------------------------------------
__global__ __launch_bounds__(256) void transpose_kernel(const float* __restrict__ x) {
    __shared__ float s[128][65];
    int bh = blockIdx.x;
    int b = bh >> 7, h = bh & 127;
    int tid = threadIdx.x;
#pragma unroll 4
    for (int step = 0; step < 32; step++) {
        int ci = step * 2 + (tid >> 7);
        int wq = tid & 127;
        s[wq][ci] = x[(((size_t)(b * C_IN + ci) * HH) + h) * WW + wq];
    }
    __syncthreads();
#pragma unroll 4
    for (int step = 0; step < 32; step++) {
        int wq = step * 4 + (tid >> 6);
        int ci = tid & 63;
        g_xh[((size_t)((b * HH + h) * WW + wq)) * C_IN + ci] = __float2half_rn(s[wq][ci]);
    }
}

// ---------------------------------------------------------------------------
// 3) Conv fp16 GEMM (m16n8k16). BM=128, BN=128, BK=64, 8 warps (2m x 4n),
//    warp 64x32. 9 chunks, 3-stage cp.async (32KB/stage), 2 CTA/SM.
//    Epilogue: y + per-(b,co) atomicMax + per-32n-segment max.
// ---------------------------------------------------------------------------
__global__ __launch_bounds__(256, 2)
void conv_mma_kernel(const float* __restrict__ bias, float* __restrict__ y) {
    extern __shared__ char smem[];
    uint32_t sbase = smem_u32(smem);

    int tid = threadIdx.x;
    int wid = tid >> 5, lane = tid & 31;
    int n0 = blockIdx.x * 128;

    // ---- B loader: 2 threads per row, 64B (4 quads) each ----
    int row = tid >> 1, half = tid & 1;
    int nld = n0 + row;
    bool valid = (nld < NTOT);
    const __half* xrow = g_xh;
    if (valid) {
        int b = nld / LL; int rem = nld - b * LL;
        int ho = rem / WO; int wo = rem - ho * WO;
        xrow = g_xh + ((size_t)(b * HH + ho) * WW + wo) * C_IN;
    }
    int rsw = row & 7;

    // ---- compute ids ----
    int mwarp = wid >> 2, nwarp = wid & 3;
    int g_id = lane >> 2, tig = lane & 3;

    float acc[4][4][4];
#pragma unroll
    for (int i = 0; i < 4; i++)
#pragma unroll
        for (int j = 0; j < 4; j++)
#pragma unroll
            for (int q = 0; q < 4; q++) acc[i][j][q] = 0.f;

    auto issue = [&](int c, int st) {
        // A: 16KB fragment-ordered, 256 threads x 64B
        const char* asrc = (const char*)(g_wAh + c * 4096) + tid * 64;
        uint32_t adst = sbase + st * STAGE + tid * 64;
#pragma unroll
        for (int q = 0; q < 4; q++) CP_A16(adst + q * 16, asrc + q * 16);
        // B: 128 rows x 128B fp16 (full pixel), quad-swizzled by row&7
        int kh = c / 3, kw = c - kh * 3;
        uint32_t bdst = sbase + st * STAGE + 16384 + row * 128;
        const __half* bs = xrow + (kh * WW + kw) * C_IN;
#pragma unroll
        for (int qi = 0; qi < 4; qi++) {
            int q = half * 4 + qi;
            int pq = q ^ rsw;
            if (valid) CP_A16(bdst + pq * 16, (const char*)(bs + q * 8));
            else       CP_A16Z(bdst + pq * 16, (const char*)bs);
        }
        CP_COMMIT();
    };

    issue(0, 0);
    issue(1, 1);

    for (int c = 0; c < NCHUNK; c++) {
        if (c + 2 < NCHUNK) {
            asm volatile("cp.async.wait_group 1;" ::: "memory");
        } else {
            asm volatile("cp.async.wait_group 0;" ::: "memory");
        }
        __syncthreads();
        if (c + 2 < NCHUNK) issue(c + 2, (c + 2) % NSTAGE);

        int st = c % NSTAGE;
        const char* Ast = smem + st * STAGE;
        const char* Arow = Ast + mwarp * 8192 + lane * 16;
        const char* Bbase = Ast + 16384 + (nwarp * 32 + g_id) * 128 + tig * 4;

#pragma unroll
        for (int ks = 0; ks < 4; ks++) {
            uint4 a[4];
#pragma unroll
            for (int mt = 0; mt < 4; mt++)
                a[mt] = *(const uint4*)(Arow + mt * 2048 + ks * 512);
            uint32_t b0[4], b1[4];
#pragma unroll
            for (int nt = 0; nt < 4; nt++) {
                b0[nt] = *(const uint32_t*)(Bbase + nt * 1024 + (((2 * ks)     ^ g_id) * 16));
                b1[nt] = *(const uint32_t*)(Bbase + nt * 1024 + (((2 * ks + 1) ^ g_id) * 16));
            }
#pragma unroll
            for (int mt = 0; mt < 4; mt++)
#pragma unroll
                for (int nt = 0; nt < 4; nt++)
                    mma16(acc[mt][nt], a[mt].x, a[mt].y, a[mt].z, a[mt].w,
                          b0[nt], b1[nt]);
        }
    }

    // ---- epilogue: y store + per-(b,co) atomicMax + segment max ----
    int nwbase = n0 + nwarp * 32;
    bool segvalid = (nwbase < NTOT);
    int seg = nwbase >> 5;
    int bA = segvalid ? (nwbase / LL) : (BATCH - 1);
#pragma unroll
    for (int mt = 0; mt < 4; mt++) {
        int co0 = mwarp * 64 + mt * 16 + g_id;
        int co1 = co0 + 8;
        float bc0 = bias[co0], bc1 = bias[co1];
        float mA0 = -FLT_MAX, mB0 = -FLT_MAX, mA1 = -FLT_MAX, mB1 = -FLT_MAX;
#pragma unroll
        for (int nt = 0; nt < 4; nt++) {
            int n = nwbase + nt * 8 + tig * 2;
            if (n >= NTOT) continue;
            int bb = n / LL;
            int l = n - bb * LL;
            size_t base = (size_t)bb * (C_OUT * LL) + l;
            float v00 = acc[mt][nt][0] + bc0, v01 = acc[mt][nt][1] + bc0;
            float v10 = acc[mt][nt][2] + bc1, v11 = acc[mt][nt][3] + bc1;
            *(float2*)&y[base + (size_t)co0 * LL] = make_float2(v00, v01);
            *(float2*)&y[base + (size_t)co1 * LL] = make_float2(v10, v11);
            float m0 = fmaxf(v00, v01), m1 = fmaxf(v10, v11);
            if (bb == bA) { mA0 = fmaxf(mA0, m0); mA1 = fmaxf(mA1, m1); }
            else          { mB0 = fmaxf(mB0, m0); mB1 = fmaxf(mB1, m1); }
        }
        mA0 = fmaxf(mA0, __shfl_xor_sync(0xffffffffu, mA0, 1));
        mA0 = fmaxf(mA0, __shfl_xor_sync(0xffffffffu, mA0, 2));
        mB0 = fmaxf(mB0, __shfl_xor_sync(0xffffffffu, mB0, 1));
        mB0 = fmaxf(mB0, __shfl_xor_sync(0xffffffffu, mB0, 2));
        mA1 = fmaxf(mA1, __shfl_xor_sync(0xffffffffu, mA1, 1));
        mA1 = fmaxf(mA1, __shfl_xor_sync(0xffffffffu, mA1, 2));
        mB1 = fmaxf(mB1, __shfl_xor_sync(0xffffffffu, mB1, 1));
        mB1 = fmaxf(mB1, __shfl_xor_sync(0xffffffffu, mB1, 2));
        if (tig == 0 && segvalid) {
            g_segmax[(size_t)co0 * NSEG + seg] = fenc(fmaxf(mA0, mB0));
            g_segmax[(size_t)co1 * NSEG + seg] = fenc(fmaxf(mA1, mB1));
            if (mA0 > -FLT_MAX) atomicMax(&g_ymax[bA * C_OUT + co0], fenc(mA0));
            if (mA1 > -FLT_MAX) atomicMax(&g_ymax[bA * C_OUT + co1], fenc(mA1));
            if (mB0 > -FLT_MAX && bA + 1 < BATCH) atomicMax(&g_ymax[(bA + 1) * C_OUT + co0], fenc(mB0));
            if (mB1 > -FLT_MAX && bA + 1 < BATCH) atomicMax(&g_ymax[(bA + 1) * C_OUT + co1], fenc(mB1));
        }
    }
}

// ---------------------------------------------------------------------------
// 4) Fused scan + exact fp32 refinement: segmax-driven candidates into smem,
//    then warp 0 computes exact dots from original NCHW x.
// ---------------------------------------------------------------------------
__global__ __launch_bounds__(256) void scanrefine_kernel(const float* __restrict__ y,
                                                         const float* __restrict__ x) {
    __shared__ int s_cnt;
    __shared__ int s_cand[CAP];
    int bc = blockIdx.x, tid = threadIdx.x;
    int b = bc >> 7, co = bc & 127;
    if (tid == 0) s_cnt = 0;
    __syncthreads();

    const float* row = y + (size_t)bc * LL;
    float thresh = fdec(g_ymax[bc]) - 0.05f;

    int n_lo = b * LL, n_hi = n_lo + LL;
    int s0 = n_lo >> 5, s1 = (n_hi - 1) >> 5;
    const unsigned* sm = &g_segmax[(size_t)co * NSEG];

    for (int s = s0 + tid; s <= s1; s += 256) {
        if (fdec(sm[s]) >= thresh) {
            int a = s * 32;      if (a < n_lo) a = n_lo;
            int e = s * 32 + 32; if (e > n_hi) e = n_hi;
            for (int n = a; n < e; n++) {
                float v = row[n - n_lo];
                if (v >= thresh) {
                    int pos = atomicAdd(&s_cnt, 1);
                    if (pos < CAP) s_cand[pos] = n - n_lo;
                }
            }
        }
    }
    __syncthreads();

    if (tid < 32) {
        int lane = tid;
        int cnt = s_cnt; if (cnt > CAP) cnt = CAP;
        float best = -FLT_MAX;
        int bi = 0x7fffffff;
        for (int idx = 0; idx < cnt; idx++) {
            int l = s_cand[idx];
            int ho = l / WO, wo = l - ho * WO;
            float acc = 0.f;
#pragma unroll
            for (int c = 0; c < 18; c++) {
                int r = c >> 1, kh = r / 3, kw = r - kh * 3;
                int ci = ((c & 1) << 5) + lane;
                acc += g_wn2[(c * C_OUT + co) * 32 + lane] *
                       x[((size_t)(b * C_IN + ci) * HH + ho + kh) * WW + wo + kw];
            }
#pragma unroll
            for (int o = 16; o > 0; o >>= 1) acc += __shfl_xor_sync(0xffffffffu, acc, o);
            if (lane == 0) {
                if (acc > best || (acc == best && l < bi)) { best = acc; bi = l; }
            }
        }
        if (lane == 0) g_winners[bc] = bi;
    }
}

// ---------------------------------------------------------------------------
// 5) delta_w[co][k] = mean_b winning patch
// ---------------------------------------------------------------------------
__global__ void deltaw_kernel(const float* __restrict__ x, float* __restrict__ out) {
    int t = blockIdx.x * blockDim.x + threadIdx.x;
    if (t >= C_OUT * KDIM) return;
    int co = t / KDIM;
    int k = t - co * KDIM;
    int ci = k / 9;
    int r = k - ci * 9;
    int kh = r / 3, kw = r - kh * 3;
    float s = 0.f;
#pragma unroll
    for (int b = 0; b < BATCH; b++) {
        int l = g_winners[b * C_OUT + co];
        int ho = l / WO;
        int wo = l - ho * WO;
        s += x[((size_t)(b * C_IN + ci) * HH + ho + kh) * WW + wo + kw];
    }
    out[(size_t)BATCH * C_OUT * LL + t] = s * (1.f / 16.f);
}

// ---------------------------------------------------------------------------
extern "C" void kernel_launch(void* const* d_in, const int* in_sizes, int n_in,
                              void* d_out, int out_size) {
    const float* x    = (const float*)d_in[0];
    const float* w    = (const float*)d_in[1];
    const float* bias = (const float*)d_in[2];
    float* out = (float*)d_out;

    cudaFuncSetAttribute(conv_mma_kernel,
                         cudaFuncAttributeMaxDynamicSharedMemorySize, NSTAGE * STAGE);

    norm_kernel<<<C_OUT, 256>>>(w);
    transpose_kernel<<<BATCH * HH, 256>>>(x);
    conv_mma_kernel<<<(NTOT + 127) / 128, 256, NSTAGE * STAGE>>>(bias, out);
    scanrefine_kernel<<<BATCH * C_OUT, 256>>>(out, x);
    deltaw_kernel<<<(C_OUT * KDIM + 255) / 256, 256>>>(x, out);
}